// round 12
// baseline (speedup 1.0000x reference)
#include <cuda_runtime.h>

// query [32, 2048] f32, W [2048, 100] f32, out [32, 100] f32.
// out[b,o] = sum_j (q[b,j] - (2048*trunc(q[b,j]) + S[b]))^2 * W[j,o]
// S[b] = sum_j trunc(q[b,j]).  Integer-exact in f32 (|values| < 2^24).

#define BATCH     32
#define NDIM      2048
#define NOUT      100
#define YSPLIT    4
#define KSPLIT    8
#define BSPLIT    4                        // batches per block
#define NBGRP     (BATCH / BSPLIT)         // 8
#define COLS_PER_BLK (NOUT / YSPLIT)       // 25
#define KCHUNK    (NDIM / KSPLIT)          // 256
#define MTHREADS  256
#define MWARPS    (MTHREADS / 32)          // 8
#define JPART     (KCHUNK / MWARPS)        // 32 j's per warp
#define PTHREADS  512

__device__ int g_S[BATCH];                 // per-batch sum of trunc(q)

// Kernel A: one block per batch. S[b] -> g_S, zero out[b,:].
__global__ __launch_bounds__(PTHREADS)
void prep_kernel(const float* __restrict__ q, float* __restrict__ out) {
    const int b    = blockIdx.x;
    const int tid  = threadIdx.x;
    const int lane = tid & 31;
    const int wrp  = tid >> 5;

    __shared__ int wsum[PTHREADS / 32];

    const float4 v = ((const float4*)(q + b * NDIM))[tid];
    const int cs = (int)v.x + (int)v.y + (int)v.z + (int)v.w;

    const int s = __reduce_add_sync(0xffffffffu, cs);
    if (lane == 0) wsum[wrp] = s;
    __syncthreads();

    if (tid == 0) {
        int S = 0;
        #pragma unroll
        for (int w = 0; w < PTHREADS / 32; w++) S += wsum[w];
        g_S[b] = S;
    }
    if (tid < NOUT) out[b * NOUT + tid] = 0.0f;
}

// Kernel B: grid (NBGRP, YSPLIT, KSPLIT). Block: 4 batches x 25 cols x 256 j.
__global__ __launch_bounds__(MTHREADS)
void matvec_kernel(const float* __restrict__ q,
                   const float* __restrict__ W,
                   float* __restrict__ out) {
    const int b0      = blockIdx.x * BSPLIT;
    const int colbase = blockIdx.y * COLS_PER_BLK;
    const int kbase   = blockIdx.z * KCHUNK;

    __shared__ float rem[BSPLIT][KCHUNK];            // 4 KB
    __shared__ float partial[MWARPS][COLS_PER_BLK][BSPLIT];  // 3.2 KB

    const int tid  = threadIdx.x;
    const int lane = tid & 31;
    const int wrp  = tid >> 5;

    // rem for 4 batches x this K-chunk (coalesced; one float per thread per batch).
    #pragma unroll
    for (int bb = 0; bb < BSPLIT; bb++) {
        const float v  = q[(b0 + bb) * NDIM + kbase + tid];
        const float Sf = (float)g_S[b0 + bb];
        const float d  = v - fmaf(2048.0f, (float)(int)v, Sf);
        rem[bb][tid] = d * d;
    }
    __syncthreads();

    // Matvec: warp -> 32-j slice, lane -> output col; each W load feeds 4 batches.
    float acc0 = 0.f, acc1 = 0.f, acc2 = 0.f, acc3 = 0.f;
    if (lane < COLS_PER_BLK) {
        const float* Wp = W + colbase + lane;
        const int j0 = wrp * JPART;
        #pragma unroll 8
        for (int i = 0; i < JPART; i++) {
            const int j = j0 + i;
            const float wv = __ldg(&Wp[(kbase + j) * NOUT]);
            acc0 = fmaf(rem[0][j], wv, acc0);
            acc1 = fmaf(rem[1][j], wv, acc1);
            acc2 = fmaf(rem[2][j], wv, acc2);
            acc3 = fmaf(rem[3][j], wv, acc3);
        }
        partial[wrp][lane][0] = acc0;
        partial[wrp][lane][1] = acc1;
        partial[wrp][lane][2] = acc2;
        partial[wrp][lane][3] = acc3;
    }
    __syncthreads();

    // Fold: threads 0..99 -> (col, bb); sum 8 warp partials; one atomic each.
    if (tid < COLS_PER_BLK * BSPLIT) {
        const int col = tid >> 2;          // 0..24
        const int bb  = tid & 3;           // 0..3
        float r = 0.0f;
        #pragma unroll
        for (int p = 0; p < MWARPS; p++) r += partial[p][col][bb];
        atomicAdd(&out[(b0 + bb) * NOUT + colbase + col], r);
    }
}

extern "C" void kernel_launch(void* const* d_in, const int* in_sizes, int n_in,
                              void* d_out, int out_size) {
    const float* q = (const float*)d_in[0];   // [32, 2048]
    const float* W = (const float*)d_in[1];   // [2048, 100]
    float* out = (float*)d_out;               // [32, 100]
    (void)in_sizes; (void)n_in; (void)out_size;

    prep_kernel<<<BATCH, PTHREADS>>>(q, out);
    dim3 grid(NBGRP, YSPLIT, KSPLIT);
    matvec_kernel<<<grid, MTHREADS>>>(q, W, out);
}

// round 14
// speedup vs baseline: 1.2657x; 1.2657x over previous
#include <cuda_runtime.h>

// query [32, 2048] f32, W [2048, 100] f32, out [32, 100] f32.
// out[b,o] = sum_j (q[b,j] - (2048*trunc(q[b,j]) + S[b]))^2 * W[j,o]
// S[b] = sum_j trunc(q[b,j]).  Integer-exact in f32 (|values| < 2^24).

#define BATCH     32
#define NDIM      2048
#define NOUT      100
#define YSPLIT    4
#define KSPLIT    8
#define BSPLIT    2                        // batches per block
#define NBGRP     (BATCH / BSPLIT)         // 16
#define COLS_PER_BLK (NOUT / YSPLIT)       // 25
#define KCHUNK    (NDIM / KSPLIT)          // 256
#define MTHREADS  512
#define MWARPS    (MTHREADS / 32)          // 16
#define JPART     (KCHUNK / MWARPS)        // 16 j's per warp
#define PTHREADS  512

__device__ int g_S[BATCH];                 // per-batch sum of trunc(q)

// Kernel A: one block per batch. S[b] -> g_S, zero out[b,:].
__global__ __launch_bounds__(PTHREADS)
void prep_kernel(const float* __restrict__ q, float* __restrict__ out) {
    const int b    = blockIdx.x;
    const int tid  = threadIdx.x;
    const int lane = tid & 31;
    const int wrp  = tid >> 5;

    __shared__ int wsum[PTHREADS / 32];

    const float4 v = ((const float4*)(q + b * NDIM))[tid];
    const int cs = (int)v.x + (int)v.y + (int)v.z + (int)v.w;

    const int s = __reduce_add_sync(0xffffffffu, cs);
    if (lane == 0) wsum[wrp] = s;
    __syncthreads();

    if (tid == 0) {
        int S = 0;
        #pragma unroll
        for (int w = 0; w < PTHREADS / 32; w++) S += wsum[w];
        g_S[b] = S;
    }
    if (tid < NOUT) out[b * NOUT + tid] = 0.0f;
}

// Kernel B: grid (16, 4, 8) = 512 blocks x 512 threads.
// Block: 2 batches x 25 cols x 256-j chunk.
__global__ __launch_bounds__(MTHREADS)
void matvec_kernel(const float* __restrict__ q,
                   const float* __restrict__ W,
                   float* __restrict__ out) {
    const int b0      = blockIdx.x * BSPLIT;
    const int colbase = blockIdx.y * COLS_PER_BLK;
    const int kbase   = blockIdx.z * KCHUNK;

    __shared__ float rem[BSPLIT][KCHUNK];                     // 2 KB
    __shared__ float partial[MWARPS][COLS_PER_BLK][BSPLIT];   // 3.2 KB

    const int tid  = threadIdx.x;
    const int lane = tid & 31;
    const int wrp  = tid >> 5;

    // rem: 512 threads cover 2 batches x 256 j, one coalesced float each.
    {
        const int bb  = tid >> 8;          // 0..1
        const int idx = tid & 255;         // 0..255
        const float v  = q[(b0 + bb) * NDIM + kbase + idx];
        const float Sf = (float)g_S[b0 + bb];
        const float d  = v - fmaf(2048.0f, (float)(int)v, Sf);
        rem[bb][idx] = d * d;
    }
    __syncthreads();

    // Matvec: warp -> 16-j slice, lane -> output col; each W load feeds 2 batches.
    if (lane < COLS_PER_BLK) {
        const float* Wp = W + colbase + lane;
        const int j0 = wrp * JPART;
        float acc0 = 0.f, acc1 = 0.f;
        #pragma unroll
        for (int i = 0; i < JPART; i++) {
            const int j = j0 + i;
            const float wv = __ldg(&Wp[(kbase + j) * NOUT]);
            acc0 = fmaf(rem[0][j], wv, acc0);
            acc1 = fmaf(rem[1][j], wv, acc1);
        }
        partial[wrp][lane][0] = acc0;
        partial[wrp][lane][1] = acc1;
    }
    __syncthreads();

    // Fold: threads 0..49 -> (col, bb); sum 16 warp partials; one atomic each.
    if (tid < COLS_PER_BLK * BSPLIT) {
        const int col = tid >> 1;          // 0..24
        const int bb  = tid & 1;           // 0..1
        float r = 0.0f;
        #pragma unroll
        for (int p = 0; p < MWARPS; p++) r += partial[p][col][bb];
        atomicAdd(&out[(b0 + bb) * NOUT + colbase + col], r);
    }
}

extern "C" void kernel_launch(void* const* d_in, const int* in_sizes, int n_in,
                              void* d_out, int out_size) {
    const float* q = (const float*)d_in[0];   // [32, 2048]
    const float* W = (const float*)d_in[1];   // [2048, 100]
    float* out = (float*)d_out;               // [32, 100]
    (void)in_sizes; (void)n_in; (void)out_size;

    prep_kernel<<<BATCH, PTHREADS>>>(q, out);
    dim3 grid(NBGRP, YSPLIT, KSPLIT);
    matvec_kernel<<<grid, MTHREADS>>>(q, W, out);
}